// round 14
// baseline (speedup 1.0000x reference)
#include <cuda_runtime.h>
#include <cuda_fp16.h>

// Fixed problem shape: N nodes == N edges, C = 64 channels.
#define NMAX 1048576
#define SCAN_CHUNK 4096               // elements per scan block
#define SCAN_NB (NMAX / SCAN_CHUNK)   // 256 scan blocks

// ---- persistent device scratch (no runtime allocation allowed) ----
// g_deg, g_state, g_bcount, g_bcur are statically zero and self-cleaned each
// call, so every graph replay sees zeros.
__device__ float  g_s[NMAX];          // s[i] = x[i] . w
__device__ float  g_learned[NMAX];    // learned edge score per node
__device__ int    g_deg[NMAX];        // in-degree histogram (self-cleaning)
__device__ int    g_rank[NMAX];       // per-edge rank within its dst row
__device__ int    g_rowptr[NMAX + 1]; // CSR row pointers (by dst)
__device__ int2   g_sd[NMAX];         // (src, dst) decoded edge list
__device__ int2   g_edge[NMAX];       // (src, bitcast(score)) sorted by dst
__device__ int2   g_nodelist[NMAX];   // (node | deg<<20, r0), grouped by degree
__device__ __half2 g_xh[(size_t)NMAX * 32];      // fp16 copy of x (rows = 32 half2)
__device__ unsigned long long g_state[SCAN_NB];  // lookback state (val<<2 | flag)
__device__ int    g_bcount[4];        // bucket sizes (deg 0,1,2,>=3)
__device__ int    g_bcur[4];          // bucket fill cursors

// K1: block-specialized [dot-product blocks || edge-decode/histogram blocks].
__global__ void k_fused1(const float* __restrict__ x,
                         const float* __restrict__ w,
                         const float* __restrict__ b,
                         const void* __restrict__ ei,
                         int n, int dotBlocks) {
    if (blockIdx.x >= dotBlocks) {      // ---- edge duty ----
        // First edge block also re-zeroes bucket counters for this call
        // (before k_fused2 accumulates them; launch order guarantees safety).
        if (blockIdx.x == dotBlocks && threadIdx.x < 4) {
            g_bcount[threadIdx.x] = 0;
            g_bcur[threadIdx.x] = 0;
        }
        // Per-block dtype detect: genuine int64 indices < 2^31 have zero high
        // words; int32 data reinterpreted as int64 has random nonzero highs.
        __shared__ int s_is64;
        if (threadIdx.x < 32) {
            unsigned long long v = ((const unsigned long long*)ei)[threadIdx.x];
            unsigned m = __ballot_sync(0xffffffffu, (v >> 32) != 0ull);
            if (threadIdx.x == 0) s_is64 = (m == 0u);
        }
        __syncthreads();
        int is64 = s_is64;
        int e0 = ((blockIdx.x - dotBlocks) * blockDim.x + threadIdx.x) * 2;
        #pragma unroll
        for (int k = 0; k < 2; k++) {
            int e = e0 + k;
            if (e >= n) return;
            int src, dst;
            if (is64) {
                src = (int)((const long long*)ei)[e];
                dst = (int)((const long long*)ei)[(size_t)n + e];
            } else {
                src = ((const int*)ei)[e];
                dst = ((const int*)ei)[(size_t)n + e];
            }
            __stcs(&g_sd[e], make_int2(src, dst));     // write-once stream
            g_rank[e] = atomicAdd(&g_deg[dst], 1);
        }
        return;
    }
    // ---- dot duty: 2 nodes/warp, float4 lanes ----
    int wrp  = blockIdx.x * (blockDim.x >> 5) + (threadIdx.x >> 5);
    int lane = threadIdx.x & 31;
    int half = lane >> 4;
    int l    = lane & 15;
    int i = wrp * 2 + half;
    if (i >= n) return;
    float4 xv = reinterpret_cast<const float4*>(x + (size_t)i * 64)[l];
    float4 wv = reinterpret_cast<const float4*>(w)[l];
    // fp16 staging copy for the gather (half the bytes, mostly L2-resident).
    __half2 ha = __floats2half2_rn(xv.x, xv.y);
    __half2 hb = __floats2half2_rn(xv.z, xv.w);
    unsigned ua = *reinterpret_cast<unsigned*>(&ha);
    unsigned ub = *reinterpret_cast<unsigned*>(&hb);
    *reinterpret_cast<uint2*>(&g_xh[(size_t)i * 32 + 2 * l]) = make_uint2(ua, ub);
    float p = xv.x * wv.x + xv.y * wv.y + xv.z * wv.z + xv.w * wv.w;
    #pragma unroll
    for (int off = 8; off; off >>= 1) p += __shfl_down_sync(0xffffffffu, p, off, 16);
    if (l == 0) {
        g_s[i] = p;
        g_learned[i] = b[0];   // self-loop contributes lin(0) = b
    }
}

// K2: block-specialized [scan blocks || learned-atomic blocks].
// Scan blocks also histogram node degrees into 4 buckets (0,1,2,>=3).
__global__ void k_fused2(const float* __restrict__ bb,
                         int n, int first) {
    if (blockIdx.x >= SCAN_NB) {        // ---- learned duty ----
        int e0 = ((blockIdx.x - SCAN_NB) * blockDim.x + threadIdx.x) * 2;
        float cb = bb[0];
        #pragma unroll
        for (int k = 0; k < 2; k++) {
            int e = e0 + k;
            if (e >= n) return;
            int2 sd = g_sd[e];
            if (sd.y >= first) {
                atomicAdd(&g_learned[sd.y], g_s[sd.x] - g_s[sd.y] + cb);
            }
        }
        return;
    }
    // ---- scan duty: decoupled-lookback exclusive scan of deg -> rowptr ----
    __shared__ int sh[256];
    __shared__ int s_off;
    __shared__ int s_b[4];
    int b = blockIdx.x, t = threadIdx.x;
    if (t < 4) s_b[t] = 0;
    int base = b * SCAN_CHUNK + t * 16;
    int4 v0 = reinterpret_cast<const int4*>(g_deg + base)[0];
    int4 v1 = reinterpret_cast<const int4*>(g_deg + base)[1];
    int4 v2 = reinterpret_cast<const int4*>(g_deg + base)[2];
    int4 v3 = reinterpret_cast<const int4*>(g_deg + base)[3];
    int loc[16] = {v0.x, v0.y, v0.z, v0.w, v1.x, v1.y, v1.z, v1.w,
                   v2.x, v2.y, v2.z, v2.w, v3.x, v3.y, v3.z, v3.w};
    int tot = 0, c0 = 0, c1 = 0, c2 = 0, c3 = 0;
    #pragma unroll
    for (int k = 0; k < 16; k++) {
        int d = loc[k];
        tot += d;
        c0 += (d == 0); c1 += (d == 1); c2 += (d == 2); c3 += (d >= 3);
    }
    sh[t] = tot;
    __syncthreads();
    if (c0) atomicAdd_block(&s_b[0], c0);
    if (c1) atomicAdd_block(&s_b[1], c1);
    if (c2) atomicAdd_block(&s_b[2], c2);
    if (c3) atomicAdd_block(&s_b[3], c3);
    for (int off = 1; off < 256; off <<= 1) {
        int add = (t >= off) ? sh[t - off] : 0;
        __syncthreads();
        sh[t] += add;
        __syncthreads();
    }
    if (t == 0) {
        int total = sh[255];
        atomicExch(&g_state[b], ((unsigned long long)total << 2) | 1ull);  // AGG
        long long sum = 0;
        for (int j = b - 1; j >= 0; ) {
            unsigned long long st;
            do { st = atomicAdd(&g_state[j], 0ull); } while ((st & 3ull) == 0ull);
            sum += (long long)(st >> 2);
            if ((st & 3ull) == 2ull) break;   // PREFIX -> done
            j--;
        }
        atomicExch(&g_state[b],
                   (((unsigned long long)(sum + total)) << 2) | 2ull);     // PREFIX
        s_off = (int)sum;
        if (b == SCAN_NB - 1) g_rowptr[n] = (int)(sum + total);
    }
    __syncthreads();
    if (t < 4) atomicAdd(&g_bcount[t], s_b[t]);
    int run = s_off + sh[t] - tot;   // exclusive prefix for this thread's chunk
    #pragma unroll
    for (int k = 0; k < 16; k++) {
        g_rowptr[base + k] = run;
        run += loc[k];
    }
    // Self-clean: zero this chunk of deg for the next call / graph replay.
    int4 z = make_int4(0, 0, 0, 0);
    reinterpret_cast<int4*>(g_deg + base)[0] = z;
    reinterpret_cast<int4*>(g_deg + base)[1] = z;
    reinterpret_cast<int4*>(g_deg + base)[2] = z;
    reinterpret_cast<int4*>(g_deg + base)[3] = z;
}

// K3: [edge blocks: score + atomic-free scatter || node blocks: build
// degree-bucketed packed node records (i | deg<<20, r0)].
__global__ void k_score_scatter(const float* __restrict__ w1,
                                const float* __restrict__ w2,
                                const float* __restrict__ w3,
                                int n, int first, int edgeBlocks) {
    if (blockIdx.x < edgeBlocks) {      // ---- edge duty ----
        if (blockIdx.x == 0 && threadIdx.x < SCAN_NB) g_state[threadIdx.x] = 0ull;
        int e0 = (blockIdx.x * blockDim.x + threadIdx.x) * 2;
        float cw1 = w1[0], cw2 = w2[0], cw3 = w3[0];
        #pragma unroll
        for (int k = 0; k < 2; k++) {
            int e = e0 + k;
            if (e >= n) return;
            float sc;
            if (e < first) {
                sc = cw1;
            } else {
                sc = (((e - first) & 1) ? cw3 : cw2) + g_learned[e];
            }
            int2 sd = __ldcs(&g_sd[e]);            // read-once stream
            int pos = g_rowptr[sd.y] + g_rank[e];
            g_edge[pos] = make_int2(sd.x, __float_as_int(sc));
        }
        return;
    }
    // ---- node duty: place 2 nodes/thread into degree buckets ----
    __shared__ int s_c[4];     // block-local bucket counts
    __shared__ int s_gb[4];    // block's global base within each bucket
    int t = threadIdx.x;
    if (t < 4) s_c[t] = 0;
    __syncthreads();
    int i0 = ((blockIdx.x - edgeBlocks) * blockDim.x + t) * 2;
    int bk[2] = {-1, -1}, lp[2] = {0, 0}, rr0[2], dd[2];
    #pragma unroll
    for (int k = 0; k < 2; k++) {
        int i = i0 + k;
        if (i < n) {
            rr0[k] = g_rowptr[i];
            int d = g_rowptr[i + 1] - rr0[k];
            dd[k] = d < 4095 ? d : 4095;   // 12-bit cap (Poisson(1) max ~12)
            int bb = d < 3 ? d : 3;
            bk[k] = bb;
            lp[k] = atomicAdd_block(&s_c[bb], 1);
        }
    }
    __syncthreads();
    if (t < 4) s_gb[t] = atomicAdd(&g_bcur[t], s_c[t]);
    __syncthreads();
    int base1 = g_bcount[0];
    int base2 = base1 + g_bcount[1];
    int base3 = base2 + g_bcount[2];
    int bases[4] = {0, base1, base2, base3};
    #pragma unroll
    for (int k = 0; k < 2; k++) {
        if (bk[k] >= 0) {
            g_nodelist[bases[bk[k]] + s_gb[bk[k]] + lp[k]] =
                make_int2((i0 + k) | (dd[k] << 20), rr0[k]);
        }
    }
}

// Convert+scale a loaded fp16 row and store it (streaming) with ReLU.
__device__ __forceinline__ void scale_store(float* __restrict__ orow,
                                            uint4 h0, uint4 h1,
                                            float v, int l) {
    unsigned hw[8] = {h0.x, h0.y, h0.z, h0.w, h1.x, h1.y, h1.z, h1.w};
    float r[16];
    #pragma unroll
    for (int k = 0; k < 8; k++) {
        float2 f = __half22float2(*reinterpret_cast<__half2*>(&hw[k]));
        r[2 * k]     = fmaxf(f.x * v, 0.f);
        r[2 * k + 1] = fmaxf(f.y * v, 0.f);
    }
    float4* o = reinterpret_cast<float4*>(orow);
    __stcs(&o[2 * l],         make_float4(r[0], r[1], r[2], r[3]));
    __stcs(&o[2 * l + 1],     make_float4(r[4], r[5], r[6], r[7]));
    __stcs(&o[8 + 2 * l],     make_float4(r[8], r[9], r[10], r[11]));
    __stcs(&o[8 + 2 * l + 1], make_float4(r[12], r[13], r[14], r[15]));
}

// Accumulate one edge's fp16 row into the 8 float2 accumulators.
__device__ __forceinline__ void acc_edge(float2 (&acc)[8], int2 ev, int l) {
    float v = __int_as_float(ev.y);
    const uint4* row = reinterpret_cast<const uint4*>(g_xh + (size_t)ev.x * 32);
    uint4 h0 = row[l];
    uint4 h1 = row[l + 4];
    unsigned hw[8] = {h0.x, h0.y, h0.z, h0.w, h1.x, h1.y, h1.z, h1.w};
    #pragma unroll
    for (int k = 0; k < 8; k++) {
        __half2 hh = *reinterpret_cast<__half2*>(&hw[k]);
        float2 f = __half22float2(hh);
        acc[k].x = fmaf(f.x, v, acc[k].x);
        acc[k].y = fmaf(f.y, v, acc[k].y);
    }
}

// Shared accumulate-epilogue (streaming stores) for deg>=2 paths.
__device__ __forceinline__ void acc_store(float* __restrict__ orow,
                                          float2 (&acc)[8], int l) {
    float4* o = reinterpret_cast<float4*>(orow);
    __stcs(&o[2 * l], make_float4(fmaxf(acc[0].x, 0.f), fmaxf(acc[0].y, 0.f),
                                  fmaxf(acc[1].x, 0.f), fmaxf(acc[1].y, 0.f)));
    __stcs(&o[2 * l + 1], make_float4(fmaxf(acc[2].x, 0.f), fmaxf(acc[2].y, 0.f),
                                      fmaxf(acc[3].x, 0.f), fmaxf(acc[3].y, 0.f)));
    __stcs(&o[8 + 2 * l], make_float4(fmaxf(acc[4].x, 0.f), fmaxf(acc[4].y, 0.f),
                                      fmaxf(acc[5].x, 0.f), fmaxf(acc[5].y, 0.f)));
    __stcs(&o[8 + 2 * l + 1], make_float4(fmaxf(acc[6].x, 0.f), fmaxf(acc[6].y, 0.f),
                                          fmaxf(acc[7].x, 0.f), fmaxf(acc[7].y, 0.f)));
}

// K4: bucket-specialized gather with streaming output stores (keeps g_xh
// resident in L2 instead of being evicted by 256MB of write-allocate).
__global__ void __launch_bounds__(256, 6)
k_gather(float* __restrict__ out, int n, int G1, int G2) {
    int c0 = g_bcount[0], c1 = g_bcount[1], c2 = g_bcount[2];
    int b2 = c0 + c1;          // start of deg2 bucket
    int b3 = b2 + c2;          // start of deg3+ bucket
    int lane = threadIdx.x & 31;
    int wib  = threadIdx.x >> 5;
    if (blockIdx.x < G1) {
        // ---- deg<=1 region: 2 slots per 4-lane group ----
        int wrp = blockIdx.x * 8 + wib;
        int g = lane >> 2, l = lane & 3;
        int sA = wrp * 16 + g * 2;
        int sB = sA + 1;
        bool vA = sA < b2, vB = sB < b2;
        if (!vA) return;
        int2 nA = __ldcs(&g_nodelist[sA]);
        int2 nB = vB ? __ldcs(&g_nodelist[sB]) : make_int2(0, 0);
        int iA = nA.x & 0xFFFFF; int dA = ((unsigned)nA.x) >> 20;
        int iB = nB.x & 0xFFFFF; int dB = ((unsigned)nB.x) >> 20;
        int2 eA = dA ? __ldcs(&g_edge[nA.y]) : make_int2(0, 0);
        int2 eB = (vB && dB) ? __ldcs(&g_edge[nB.y]) : make_int2(0, 0);
        float fvA = dA ? __int_as_float(eA.y) : 0.f;
        float fvB = (vB && dB) ? __int_as_float(eB.y) : 0.f;
        const uint4* rowA = reinterpret_cast<const uint4*>(g_xh + (size_t)eA.x * 32);
        const uint4* rowB = reinterpret_cast<const uint4*>(g_xh + (size_t)eB.x * 32);
        uint4 a0 = rowA[l], a1 = rowA[l + 4];
        uint4 c0v = rowB[l], c1v = rowB[l + 4];
        scale_store(out + (size_t)iA * 64, a0, a1, fvA, l);
        if (vB) scale_store(out + (size_t)iB * 64, c0v, c1v, fvB, l);
        return;
    }
    int q = lane >> 2, l = lane & 3;
    if (blockIdx.x < G1 + G2) {
        // ---- deg==2 region ----
        int wrp = (blockIdx.x - G1) * 8 + wib;
        int slot = b2 + wrp * 8 + q;
        if (slot >= b3) return;
        int2 ni = __ldcs(&g_nodelist[slot]);
        int i  = ni.x & 0xFFFFF;
        int r0 = ni.y;
        int2 evA = __ldcs(&g_edge[r0]);
        int2 evB = __ldcs(&g_edge[r0 + 1]);
        float vA = __int_as_float(evA.y);
        float vB = __int_as_float(evB.y);
        const uint4* rowA = reinterpret_cast<const uint4*>(g_xh + (size_t)evA.x * 32);
        const uint4* rowB = reinterpret_cast<const uint4*>(g_xh + (size_t)evB.x * 32);
        uint4 a0 = rowA[l], a1 = rowA[l + 4];
        uint4 b0 = rowB[l], b1 = rowB[l + 4];
        unsigned ha[8] = {a0.x, a0.y, a0.z, a0.w, a1.x, a1.y, a1.z, a1.w};
        unsigned hb[8] = {b0.x, b0.y, b0.z, b0.w, b1.x, b1.y, b1.z, b1.w};
        float2 acc[8];
        #pragma unroll
        for (int k = 0; k < 8; k++) {
            float2 fa = __half22float2(*reinterpret_cast<__half2*>(&ha[k]));
            float2 fb = __half22float2(*reinterpret_cast<__half2*>(&hb[k]));
            acc[k].x = fmaf(fa.x, vA, fb.x * vB);
            acc[k].y = fmaf(fa.y, vA, fb.y * vB);
        }
        acc_store(out + (size_t)i * 64, acc, l);
        return;
    }
    // ---- deg>=3 region ----
    int wrp = (blockIdx.x - G1 - G2) * 8 + wib;
    int slot = b3 + wrp * 8 + q;
    if (slot >= n) return;
    int2 ni = __ldcs(&g_nodelist[slot]);
    int i   = ni.x & 0xFFFFF;
    int deg = ((unsigned)ni.x) >> 20;
    int r0  = ni.y;
    int r1  = r0 + deg;
    float2 acc[8];
    #pragma unroll
    for (int k = 0; k < 8; k++) acc[k] = make_float2(0.f, 0.f);
    int2 ev = __ldcs(&g_edge[r0]);
    for (int p = r0; p < r1; p++) {
        int2 evn;
        if (p + 1 < r1) evn = __ldcs(&g_edge[p + 1]);   // prefetch next record
        acc_edge(acc, ev, l);
        ev = evn;
    }
    acc_store(out + (size_t)i * 64, acc, l);
}

extern "C" void kernel_launch(void* const* d_in, const int* in_sizes, int n_in,
                              void* d_out, int out_size) {
    const float* x     = (const float*)d_in[0];
    const float* lin_w = (const float*)d_in[1];
    const float* lin_b = (const float*)d_in[2];
    const float* w1    = (const float*)d_in[3];
    const float* w2    = (const float*)d_in[4];
    const float* w3    = (const float*)d_in[5];
    const void*  ei    = d_in[6];
    float* out = (float*)d_out;

    int n = in_sizes[6] / 2;     // edge_index is (2, N)
    int first = n / 3;

    int dotBlocks  = (n + 15) / 16;         // 8 warps/block, 2 nodes/warp
    int edgeBlocks = (n + 511) / 512;       // 2 edges/thread
    int nodeBlocks = (n + 511) / 512;       // 2 nodes/thread
    // Gather regions (host-side upper bounds on bucket sizes):
    int G1 = (n + 127) / 128;               // deg<=1: 128 nodes/block
    int G2 = (n / 2 + 63) / 64;             // deg==2: <= n/2 nodes, 64/block
    int G3 = (n / 3 + 63) / 64;             // deg>=3: <= n/3 nodes, 64/block

    k_fused1       <<<dotBlocks + edgeBlocks, 256>>>(x, lin_w, lin_b, ei, n, dotBlocks);
    k_fused2       <<<SCAN_NB + edgeBlocks, 256>>>(lin_b, n, first);
    k_score_scatter<<<edgeBlocks + nodeBlocks, 256>>>(w1, w2, w3, n, first, edgeBlocks);
    k_gather       <<<G1 + G2 + G3, 256>>>(out, n, G1, G2);
}

// round 15
// speedup vs baseline: 1.0103x; 1.0103x over previous
#include <cuda_runtime.h>
#include <cuda_fp16.h>

// Fixed problem shape: N nodes == N edges, C = 64 channels.
#define NMAX 1048576
#define SCAN_CHUNK 4096               // elements per scan block
#define SCAN_NB (NMAX / SCAN_CHUNK)   // 256 scan blocks

// ---- persistent device scratch (no runtime allocation allowed) ----
// g_deg, g_state, g_bcount, g_bcur are statically zero and self-cleaned each
// call, so every graph replay sees zeros.
__device__ float  g_s[NMAX];          // s[i] = x[i] . w
__device__ float  g_learned[NMAX];    // learned edge score per node
__device__ int    g_deg[NMAX];        // in-degree histogram (self-cleaning)
__device__ int    g_rowptr[NMAX + 1]; // CSR row pointers (by dst)
__device__ int2   g_sd[NMAX];         // (src | rank<<20, dst) decoded edges
__device__ int2   g_edge[NMAX];       // (src, bitcast(score)) sorted by dst
__device__ int2   g_nodelist[NMAX];   // (node | deg<<20, r0), grouped by degree
__device__ __half2 g_xh[(size_t)NMAX * 32];      // fp16 copy of x (rows = 32 half2)
__device__ unsigned long long g_state[SCAN_NB];  // lookback state (val<<2 | flag)
__device__ int    g_bcount[4];        // bucket sizes (deg 0,1,2,>=3)
__device__ int    g_bcur[4];          // bucket fill cursors

// K1: block-specialized [dot-product blocks || edge-decode/histogram blocks].
// Edge duty packs the degree-atomic's return (the edge's rank within its dst
// row) into the high bits of the src word: src is exactly 20 bits (N = 2^20),
// rank <= ~14 whp for Poisson(1) in-degrees (12 bits available).
__global__ void k_fused1(const float* __restrict__ x,
                         const float* __restrict__ w,
                         const float* __restrict__ b,
                         const void* __restrict__ ei,
                         int n, int dotBlocks) {
    if (blockIdx.x >= dotBlocks) {      // ---- edge duty ----
        // First edge block re-zeroes bucket counters for this call
        // (before k_fused2 accumulates them; launch order guarantees safety).
        if (blockIdx.x == dotBlocks && threadIdx.x < 4) {
            g_bcount[threadIdx.x] = 0;
            g_bcur[threadIdx.x] = 0;
        }
        // Per-block dtype detect: genuine int64 indices < 2^31 have zero high
        // words; int32 data reinterpreted as int64 has random nonzero highs.
        __shared__ int s_is64;
        if (threadIdx.x < 32) {
            unsigned long long v = ((const unsigned long long*)ei)[threadIdx.x];
            unsigned m = __ballot_sync(0xffffffffu, (v >> 32) != 0ull);
            if (threadIdx.x == 0) s_is64 = (m == 0u);
        }
        __syncthreads();
        int is64 = s_is64;
        int e0 = ((blockIdx.x - dotBlocks) * blockDim.x + threadIdx.x) * 2;
        #pragma unroll
        for (int k = 0; k < 2; k++) {
            int e = e0 + k;
            if (e >= n) return;
            int src, dst;
            if (is64) {
                src = (int)((const long long*)ei)[e];
                dst = (int)((const long long*)ei)[(size_t)n + e];
            } else {
                src = ((const int*)ei)[e];
                dst = ((const int*)ei)[(size_t)n + e];
            }
            int rank = atomicAdd(&g_deg[dst], 1);
            g_sd[e] = make_int2(src | (rank << 20), dst);
        }
        return;
    }
    // ---- dot duty: 2 nodes/warp, float4 lanes ----
    int wrp  = blockIdx.x * (blockDim.x >> 5) + (threadIdx.x >> 5);
    int lane = threadIdx.x & 31;
    int half = lane >> 4;
    int l    = lane & 15;
    int i = wrp * 2 + half;
    if (i >= n) return;
    float4 xv = reinterpret_cast<const float4*>(x + (size_t)i * 64)[l];
    float4 wv = reinterpret_cast<const float4*>(w)[l];
    // fp16 staging copy for the gather (half the bytes, mostly L2-resident).
    __half2 ha = __floats2half2_rn(xv.x, xv.y);
    __half2 hb = __floats2half2_rn(xv.z, xv.w);
    unsigned ua = *reinterpret_cast<unsigned*>(&ha);
    unsigned ub = *reinterpret_cast<unsigned*>(&hb);
    *reinterpret_cast<uint2*>(&g_xh[(size_t)i * 32 + 2 * l]) = make_uint2(ua, ub);
    float p = xv.x * wv.x + xv.y * wv.y + xv.z * wv.z + xv.w * wv.w;
    #pragma unroll
    for (int off = 8; off; off >>= 1) p += __shfl_down_sync(0xffffffffu, p, off, 16);
    if (l == 0) {
        g_s[i] = p;
        g_learned[i] = b[0];   // self-loop contributes lin(0) = b
    }
}

// K2: block-specialized [scan blocks || learned-atomic blocks].
// Scan blocks also histogram node degrees into 4 buckets (0,1,2,>=3).
__global__ void k_fused2(const float* __restrict__ bb,
                         int n, int first) {
    if (blockIdx.x >= SCAN_NB) {        // ---- learned duty: 4 edges/thread ----
        int e0 = ((blockIdx.x - SCAN_NB) * blockDim.x + threadIdx.x) * 4;
        float cb = bb[0];
        #pragma unroll
        for (int k = 0; k < 4; k++) {
            int e = e0 + k;
            if (e >= n) return;
            int2 sd = g_sd[e];
            int src = sd.x & 0xFFFFF;
            if (sd.y >= first) {
                atomicAdd(&g_learned[sd.y], g_s[src] - g_s[sd.y] + cb);
            }
        }
        return;
    }
    // ---- scan duty: decoupled-lookback exclusive scan of deg -> rowptr ----
    __shared__ int sh[256];
    __shared__ int s_off;
    __shared__ int s_b[4];
    int b = blockIdx.x, t = threadIdx.x;
    if (t < 4) s_b[t] = 0;
    int base = b * SCAN_CHUNK + t * 16;
    int4 v0 = reinterpret_cast<const int4*>(g_deg + base)[0];
    int4 v1 = reinterpret_cast<const int4*>(g_deg + base)[1];
    int4 v2 = reinterpret_cast<const int4*>(g_deg + base)[2];
    int4 v3 = reinterpret_cast<const int4*>(g_deg + base)[3];
    int loc[16] = {v0.x, v0.y, v0.z, v0.w, v1.x, v1.y, v1.z, v1.w,
                   v2.x, v2.y, v2.z, v2.w, v3.x, v3.y, v3.z, v3.w};
    int tot = 0, c0 = 0, c1 = 0, c2 = 0, c3 = 0;
    #pragma unroll
    for (int k = 0; k < 16; k++) {
        int d = loc[k];
        tot += d;
        c0 += (d == 0); c1 += (d == 1); c2 += (d == 2); c3 += (d >= 3);
    }
    sh[t] = tot;
    __syncthreads();
    if (c0) atomicAdd_block(&s_b[0], c0);
    if (c1) atomicAdd_block(&s_b[1], c1);
    if (c2) atomicAdd_block(&s_b[2], c2);
    if (c3) atomicAdd_block(&s_b[3], c3);
    for (int off = 1; off < 256; off <<= 1) {
        int add = (t >= off) ? sh[t - off] : 0;
        __syncthreads();
        sh[t] += add;
        __syncthreads();
    }
    if (t == 0) {
        int total = sh[255];
        atomicExch(&g_state[b], ((unsigned long long)total << 2) | 1ull);  // AGG
        long long sum = 0;
        for (int j = b - 1; j >= 0; ) {
            unsigned long long st;
            do { st = atomicAdd(&g_state[j], 0ull); } while ((st & 3ull) == 0ull);
            sum += (long long)(st >> 2);
            if ((st & 3ull) == 2ull) break;   // PREFIX -> done
            j--;
        }
        atomicExch(&g_state[b],
                   (((unsigned long long)(sum + total)) << 2) | 2ull);     // PREFIX
        s_off = (int)sum;
        if (b == SCAN_NB - 1) g_rowptr[n] = (int)(sum + total);
    }
    __syncthreads();
    if (t < 4) atomicAdd(&g_bcount[t], s_b[t]);
    int run = s_off + sh[t] - tot;   // exclusive prefix for this thread's chunk
    #pragma unroll
    for (int k = 0; k < 16; k++) {
        g_rowptr[base + k] = run;
        run += loc[k];
    }
    // Self-clean: zero this chunk of deg for the next call / graph replay.
    int4 z = make_int4(0, 0, 0, 0);
    reinterpret_cast<int4*>(g_deg + base)[0] = z;
    reinterpret_cast<int4*>(g_deg + base)[1] = z;
    reinterpret_cast<int4*>(g_deg + base)[2] = z;
    reinterpret_cast<int4*>(g_deg + base)[3] = z;
}

// K3: [edge blocks: score + atomic-free scatter (4 edges/thread, rank comes
// packed in g_sd) || node blocks: build degree-bucketed node records].
__global__ void k_score_scatter(const float* __restrict__ w1,
                                const float* __restrict__ w2,
                                const float* __restrict__ w3,
                                int n, int first, int edgeBlocks) {
    if (blockIdx.x < edgeBlocks) {      // ---- edge duty ----
        if (blockIdx.x == 0 && threadIdx.x < SCAN_NB) g_state[threadIdx.x] = 0ull;
        int e0 = (blockIdx.x * blockDim.x + threadIdx.x) * 4;
        float cw1 = w1[0], cw2 = w2[0], cw3 = w3[0];
        #pragma unroll
        for (int k = 0; k < 4; k++) {
            int e = e0 + k;
            if (e >= n) return;
            float sc;
            if (e < first) {
                sc = cw1;
            } else {
                sc = (((e - first) & 1) ? cw3 : cw2) + g_learned[e];
            }
            int2 sd = g_sd[e];
            int src  = sd.x & 0xFFFFF;
            int rank = ((unsigned)sd.x) >> 20;
            int pos = g_rowptr[sd.y] + rank;
            g_edge[pos] = make_int2(src, __float_as_int(sc));
        }
        return;
    }
    // ---- node duty: place 2 nodes/thread into degree buckets ----
    __shared__ int s_c[4];     // block-local bucket counts
    __shared__ int s_gb[4];    // block's global base within each bucket
    int t = threadIdx.x;
    if (t < 4) s_c[t] = 0;
    __syncthreads();
    int i0 = ((blockIdx.x - edgeBlocks) * blockDim.x + t) * 2;
    int bk[2] = {-1, -1}, lp[2] = {0, 0}, rr0[2], dd[2];
    #pragma unroll
    for (int k = 0; k < 2; k++) {
        int i = i0 + k;
        if (i < n) {
            rr0[k] = g_rowptr[i];
            int d = g_rowptr[i + 1] - rr0[k];
            dd[k] = d < 4095 ? d : 4095;   // 12-bit cap (Poisson(1) max ~12)
            int bb = d < 3 ? d : 3;
            bk[k] = bb;
            lp[k] = atomicAdd_block(&s_c[bb], 1);
        }
    }
    __syncthreads();
    if (t < 4) s_gb[t] = atomicAdd(&g_bcur[t], s_c[t]);
    __syncthreads();
    int base1 = g_bcount[0];
    int base2 = base1 + g_bcount[1];
    int base3 = base2 + g_bcount[2];
    int bases[4] = {0, base1, base2, base3};
    #pragma unroll
    for (int k = 0; k < 2; k++) {
        if (bk[k] >= 0) {
            g_nodelist[bases[bk[k]] + s_gb[bk[k]] + lp[k]] =
                make_int2((i0 + k) | (dd[k] << 20), rr0[k]);
        }
    }
}

// Convert+scale a loaded fp16 row and store it with ReLU (deg<=1 fast path).
__device__ __forceinline__ void scale_store(float* __restrict__ orow,
                                            uint4 h0, uint4 h1,
                                            float v, int l) {
    unsigned hw[8] = {h0.x, h0.y, h0.z, h0.w, h1.x, h1.y, h1.z, h1.w};
    float r[16];
    #pragma unroll
    for (int k = 0; k < 8; k++) {
        float2 f = __half22float2(*reinterpret_cast<__half2*>(&hw[k]));
        r[2 * k]     = fmaxf(f.x * v, 0.f);
        r[2 * k + 1] = fmaxf(f.y * v, 0.f);
    }
    float4* o = reinterpret_cast<float4*>(orow);
    o[2 * l]         = make_float4(r[0], r[1], r[2], r[3]);
    o[2 * l + 1]     = make_float4(r[4], r[5], r[6], r[7]);
    o[8 + 2 * l]     = make_float4(r[8], r[9], r[10], r[11]);
    o[8 + 2 * l + 1] = make_float4(r[12], r[13], r[14], r[15]);
}

// Accumulate one edge's fp16 row into the 8 float2 accumulators.
__device__ __forceinline__ void acc_edge(float2 (&acc)[8], int2 ev, int l) {
    float v = __int_as_float(ev.y);
    const uint4* row = reinterpret_cast<const uint4*>(g_xh + (size_t)ev.x * 32);
    uint4 h0 = row[l];
    uint4 h1 = row[l + 4];
    unsigned hw[8] = {h0.x, h0.y, h0.z, h0.w, h1.x, h1.y, h1.z, h1.w};
    #pragma unroll
    for (int k = 0; k < 8; k++) {
        __half2 hh = *reinterpret_cast<__half2*>(&hw[k]);
        float2 f = __half22float2(hh);
        acc[k].x = fmaf(f.x, v, acc[k].x);
        acc[k].y = fmaf(f.y, v, acc[k].y);
    }
}

// Shared accumulate-epilogue for deg>=2 paths.
__device__ __forceinline__ void acc_store(float* __restrict__ orow,
                                          float2 (&acc)[8], int l) {
    float4* o = reinterpret_cast<float4*>(orow);
    o[2 * l] = make_float4(fmaxf(acc[0].x, 0.f), fmaxf(acc[0].y, 0.f),
                           fmaxf(acc[1].x, 0.f), fmaxf(acc[1].y, 0.f));
    o[2 * l + 1] = make_float4(fmaxf(acc[2].x, 0.f), fmaxf(acc[2].y, 0.f),
                               fmaxf(acc[3].x, 0.f), fmaxf(acc[3].y, 0.f));
    o[8 + 2 * l] = make_float4(fmaxf(acc[4].x, 0.f), fmaxf(acc[4].y, 0.f),
                               fmaxf(acc[5].x, 0.f), fmaxf(acc[5].y, 0.f));
    o[8 + 2 * l + 1] = make_float4(fmaxf(acc[6].x, 0.f), fmaxf(acc[6].y, 0.f),
                                   fmaxf(acc[7].x, 0.f), fmaxf(acc[7].y, 0.f));
}

// K4: bucket-specialized gather (regioned; no cache hints — best measured).
__global__ void __launch_bounds__(256, 6)
k_gather(float* __restrict__ out, int n, int G1, int G2) {
    int c0 = g_bcount[0], c1 = g_bcount[1], c2 = g_bcount[2];
    int b2 = c0 + c1;          // start of deg2 bucket
    int b3 = b2 + c2;          // start of deg3+ bucket
    int lane = threadIdx.x & 31;
    int wib  = threadIdx.x >> 5;
    if (blockIdx.x < G1) {
        // ---- deg<=1 region: 2 slots per 4-lane group ----
        int wrp = blockIdx.x * 8 + wib;
        int g = lane >> 2, l = lane & 3;
        int sA = wrp * 16 + g * 2;
        int sB = sA + 1;
        bool vA = sA < b2, vB = sB < b2;
        if (!vA) return;
        int2 nA = g_nodelist[sA];
        int2 nB = vB ? g_nodelist[sB] : make_int2(0, 0);
        int iA = nA.x & 0xFFFFF; int dA = ((unsigned)nA.x) >> 20;
        int iB = nB.x & 0xFFFFF; int dB = ((unsigned)nB.x) >> 20;
        int2 eA = dA ? g_edge[nA.y] : make_int2(0, 0);
        int2 eB = (vB && dB) ? g_edge[nB.y] : make_int2(0, 0);
        float fvA = dA ? __int_as_float(eA.y) : 0.f;
        float fvB = (vB && dB) ? __int_as_float(eB.y) : 0.f;
        const uint4* rowA = reinterpret_cast<const uint4*>(g_xh + (size_t)eA.x * 32);
        const uint4* rowB = reinterpret_cast<const uint4*>(g_xh + (size_t)eB.x * 32);
        uint4 a0 = rowA[l], a1 = rowA[l + 4];
        uint4 c0v = rowB[l], c1v = rowB[l + 4];
        scale_store(out + (size_t)iA * 64, a0, a1, fvA, l);
        if (vB) scale_store(out + (size_t)iB * 64, c0v, c1v, fvB, l);
        return;
    }
    int q = lane >> 2, l = lane & 3;
    if (blockIdx.x < G1 + G2) {
        // ---- deg==2 region ----
        int wrp = (blockIdx.x - G1) * 8 + wib;
        int slot = b2 + wrp * 8 + q;
        if (slot >= b3) return;
        int2 ni = g_nodelist[slot];
        int i  = ni.x & 0xFFFFF;
        int r0 = ni.y;
        int2 evA = g_edge[r0];
        int2 evB = g_edge[r0 + 1];
        float vA = __int_as_float(evA.y);
        float vB = __int_as_float(evB.y);
        const uint4* rowA = reinterpret_cast<const uint4*>(g_xh + (size_t)evA.x * 32);
        const uint4* rowB = reinterpret_cast<const uint4*>(g_xh + (size_t)evB.x * 32);
        uint4 a0 = rowA[l], a1 = rowA[l + 4];
        uint4 b0 = rowB[l], b1 = rowB[l + 4];
        unsigned ha[8] = {a0.x, a0.y, a0.z, a0.w, a1.x, a1.y, a1.z, a1.w};
        unsigned hb[8] = {b0.x, b0.y, b0.z, b0.w, b1.x, b1.y, b1.z, b1.w};
        float2 acc[8];
        #pragma unroll
        for (int k = 0; k < 8; k++) {
            float2 fa = __half22float2(*reinterpret_cast<__half2*>(&ha[k]));
            float2 fb = __half22float2(*reinterpret_cast<__half2*>(&hb[k]));
            acc[k].x = fmaf(fa.x, vA, fb.x * vB);
            acc[k].y = fmaf(fa.y, vA, fb.y * vB);
        }
        acc_store(out + (size_t)i * 64, acc, l);
        return;
    }
    // ---- deg>=3 region ----
    int wrp = (blockIdx.x - G1 - G2) * 8 + wib;
    int slot = b3 + wrp * 8 + q;
    if (slot >= n) return;
    int2 ni = g_nodelist[slot];
    int i   = ni.x & 0xFFFFF;
    int deg = ((unsigned)ni.x) >> 20;
    int r0  = ni.y;
    int r1  = r0 + deg;
    float2 acc[8];
    #pragma unroll
    for (int k = 0; k < 8; k++) acc[k] = make_float2(0.f, 0.f);
    int2 ev = g_edge[r0];
    for (int p = r0; p < r1; p++) {
        int2 evn;
        if (p + 1 < r1) evn = g_edge[p + 1];   // prefetch next record
        acc_edge(acc, ev, l);
        ev = evn;
    }
    acc_store(out + (size_t)i * 64, acc, l);
}

extern "C" void kernel_launch(void* const* d_in, const int* in_sizes, int n_in,
                              void* d_out, int out_size) {
    const float* x     = (const float*)d_in[0];
    const float* lin_w = (const float*)d_in[1];
    const float* lin_b = (const float*)d_in[2];
    const float* w1    = (const float*)d_in[3];
    const float* w2    = (const float*)d_in[4];
    const float* w3    = (const float*)d_in[5];
    const void*  ei    = d_in[6];
    float* out = (float*)d_out;

    int n = in_sizes[6] / 2;     // edge_index is (2, N)
    int first = n / 3;

    int dotBlocks   = (n + 15) / 16;        // 8 warps/block, 2 nodes/warp
    int edgeBlocks2 = (n + 511) / 512;      // 2 edges/thread (fused1)
    int edgeBlocks4 = (n + 1023) / 1024;    // 4 edges/thread (fused2, K3)
    int nodeBlocks  = (n + 511) / 512;      // 2 nodes/thread
    // Gather regions (host-side upper bounds on bucket sizes):
    int G1 = (n + 127) / 128;               // deg<=1: 128 nodes/block
    int G2 = (n / 2 + 63) / 64;             // deg==2: <= n/2 nodes, 64/block
    int G3 = (n / 3 + 63) / 64;             // deg>=3: <= n/3 nodes, 64/block

    k_fused1       <<<dotBlocks + edgeBlocks2, 256>>>(x, lin_w, lin_b, ei, n, dotBlocks);
    k_fused2       <<<SCAN_NB + edgeBlocks4, 256>>>(lin_b, n, first);
    k_score_scatter<<<edgeBlocks4 + nodeBlocks, 256>>>(w1, w2, w3, n, first, edgeBlocks4);
    k_gather       <<<G1 + G2 + G3, 256>>>(out, n, G1, G2);
}